// round 17
// baseline (speedup 1.0000x reference)
#include <cuda_runtime.h>

// Shapes: seq=64 steps (orig B), only batch-row t=255 of T=256 matters.
#define STEPS 64
#define HID   1024
#define G4    4096
#define TT    256
#define DD    1024
#define CC    27
#define NB    128          // recurrence CTAs (1/SM, co-resident)
#define NCH   8            // GEMM K-split chunks
#define KC    128          // k per chunk
#define SENT  0xFFC0DEADu  // NaN payload: impossible LSTM output bit pattern

typedef unsigned long long ull;
typedef unsigned int uint;

// ---- scratch (device globals; no allocation) ----
__device__ __align__(16) float g_xgp[(long)NCH * STEPS * G4];  // gate-preact partials
__device__ __align__(16) float g_h1 [STEPS * HID];
__device__ __align__(16) float g_h2 [STEPS * HID];
__device__ __align__(16) float g_zp [NCH * STEPS * 512];       // fc1 partials

__device__ __forceinline__ float sigf(float x)     { return 1.0f / (1.0f + __expf(-x)); }
__device__ __forceinline__ float tanhfast(float x) { return 2.0f / (1.0f + __expf(-2.0f * x)) - 1.0f; }

__device__ __forceinline__ ull fma2(ull a, ull b, ull c) {
    ull d;
    asm("fma.rn.f32x2 %0, %1, %2, %3;" : "=l"(d) : "l"(a), "l"(b), "l"(c));
    return d;
}
__device__ __forceinline__ float2 unpack2(ull v) {
    float2 f;
    asm("mov.b64 {%0, %1}, %2;" : "=f"(f.x), "=f"(f.y) : "l"(v));
    return f;
}
// morally-strong relaxed atomics (gpu scope) for all racing accesses
__device__ __forceinline__ ull ld_relaxed_b64(const ull* p) {
    ull v;
    asm volatile("ld.relaxed.gpu.global.b64 %0, [%1];" : "=l"(v) : "l"(p) : "memory");
    return v;
}
__device__ __forceinline__ void st_relaxed_f32(float* p, float v) {
    asm volatile("st.relaxed.gpu.global.f32 [%0], %1;" :: "l"(p), "f"(v) : "memory");
}
__device__ __forceinline__ void cp_async16(void* smem_dst, const void* gptr) {
    uint a = (uint)__cvta_generic_to_shared(smem_dst);
    asm volatile("cp.async.cg.shared.global [%0], [%1], 16;" :: "r"(a), "l"(gptr) : "memory");
}
#define CP_COMMIT() asm volatile("cp.async.commit_group;" ::: "memory")
#define CP_WAIT(n)  asm volatile("cp.async.wait_group " #n ";" ::: "memory")

// ============================================================
// gemm0: layer-1 xg partials (X = x[:,255,:]) — R16 pipeline,
// plus sentinel-fill of g_h1/g_h2 folded into the prologue.
// grid 1024 (128 rowtiles x 8 chunks), 128 threads.
// ============================================================
__global__ __launch_bounds__(128)
void gemm0_k(const float* __restrict__ X, const float* __restrict__ W)
{
    __shared__ __align__(16) float WsR[2][32 * 36];
    __shared__ __align__(16) float Xs [2][32][68];

    // folded reset: each block writes 128 sentinel words
    {
        int b = blockIdx.x, idx = b * 128 + threadIdx.x;
        if (b < 512) ((uint*)g_h1)[idx] = SENT;
        else         ((uint*)g_h2)[idx - 65536] = SENT;
    }

    const long xbase = 255L * DD;
    const long xstride = (long)TT * DD;
    float* pout = g_xgp;
    const int nrows = G4;

    const int chunk = blockIdx.x / 128;
    const int rb    = (blockIdx.x % 128) * 32;
    pout += (long)chunk * STEPS * nrows;

    const int t  = threadIdx.x;
    const int tr = t >> 4;
    const int tc = t & 15;
    const int k0 = chunk * KC;

    const int wr0 = t >> 3,          wk0 = (t & 7) * 4;
    const int wr1 = (t + 128) >> 3,  wk1 = ((t + 128) & 7) * 4;
    int xs_s[4], xs_kq[4];
#pragma unroll
    for (int i = 0; i < 4; i++) { int e = t + i * 128; xs_s[i] = e >> 3; xs_kq[i] = (e & 7) * 4; }

    cp_async16(&WsR[0][wr0 * 36 + wk0], &W[(long)(rb + wr0) * 1024 + k0 + wk0]);
    cp_async16(&WsR[0][wr1 * 36 + wk1], &W[(long)(rb + wr1) * 1024 + k0 + wk1]);
    CP_COMMIT();
    float4 xA[4];
#pragma unroll
    for (int i = 0; i < 4; i++)
        xA[i] = *(const float4*)&X[xbase + (long)xs_s[i] * xstride + k0 + xs_kq[i]];

    float acc[4][4];
#pragma unroll
    for (int i = 0; i < 4; i++)
#pragma unroll
        for (int j = 0; j < 4; j++) acc[i][j] = 0.0f;

#pragma unroll
    for (int tile = 0; tile < 4; tile++) {
        const int buf = tile & 1;
#pragma unroll
        for (int i = 0; i < 4; i++) {
            Xs[buf][xs_kq[i] + 0][xs_s[i]] = xA[i].x;
            Xs[buf][xs_kq[i] + 1][xs_s[i]] = xA[i].y;
            Xs[buf][xs_kq[i] + 2][xs_s[i]] = xA[i].z;
            Xs[buf][xs_kq[i] + 3][xs_s[i]] = xA[i].w;
        }
        if (tile < 3) {
            const int kt = k0 + (tile + 1) * 32;
            cp_async16(&WsR[buf ^ 1][wr0 * 36 + wk0], &W[(long)(rb + wr0) * 1024 + kt + wk0]);
            cp_async16(&WsR[buf ^ 1][wr1 * 36 + wk1], &W[(long)(rb + wr1) * 1024 + kt + wk1]);
            CP_COMMIT();
            CP_WAIT(1);
        } else {
            CP_WAIT(0);
        }
        __syncthreads();

        if (tile < 3) {
            const int kt = k0 + (tile + 1) * 32;
#pragma unroll
            for (int i = 0; i < 4; i++)
                xA[i] = *(const float4*)&X[xbase + (long)xs_s[i] * xstride + kt + xs_kq[i]];
        }

#pragma unroll
        for (int kq = 0; kq < 8; kq++) {
            float xf[4][4];
#pragma unroll
            for (int q = 0; q < 4; q++) {
                float4 v = *(const float4*)&Xs[buf][kq * 4 + q][tc * 4];
                xf[q][0] = v.x; xf[q][1] = v.y; xf[q][2] = v.z; xf[q][3] = v.w;
            }
            float wf[4][4];
#pragma unroll
            for (int i = 0; i < 4; i++) {
                float4 v = *(const float4*)&WsR[buf][(tr * 4 + i) * 36 + kq * 4];
                wf[i][0] = v.x; wf[i][1] = v.y; wf[i][2] = v.z; wf[i][3] = v.w;
            }
#pragma unroll
            for (int i = 0; i < 4; i++)
#pragma unroll
                for (int j = 0; j < 4; j++) {
                    acc[i][j] = fmaf(wf[i][0], xf[0][j], acc[i][j]);
                    acc[i][j] = fmaf(wf[i][1], xf[1][j], acc[i][j]);
                    acc[i][j] = fmaf(wf[i][2], xf[2][j], acc[i][j]);
                    acc[i][j] = fmaf(wf[i][3], xf[3][j], acc[i][j]);
                }
        }
        __syncthreads();
    }

    // coalesced output via smem transpose
    {
        float (*ob)[68] = Xs[0];
#pragma unroll
        for (int i = 0; i < 4; i++)
            *(float4*)&ob[tr * 4 + i][tc * 4] =
                make_float4(acc[i][0], acc[i][1], acc[i][2], acc[i][3]);
        __syncthreads();
        const int s_i = t >> 1, half = t & 1;
#pragma unroll
        for (int q = 0; q < 4; q++) {
            const int row = half * 16 + q * 4;
            float4 o = make_float4(ob[row + 0][s_i], ob[row + 1][s_i],
                                   ob[row + 2][s_i], ob[row + 3][s_i]);
            *(float4*)&pout[(long)s_i * nrows + rb + row] = o;
        }
    }
}

// ============================================================
// gemmov: PDL-overlapped GEMM. X = a (possibly in-flight) h buffer,
// read via sentinel-polled relaxed b64 + nanosleep backoff.
// Each CTA: one 32-row tile x 4 k-chunks; ALL W cp.async'd up front
// into dynamic smem (streams during the overlapped recurrence).
//   layer-2 xg: grid 256 (ntiles=128), nrows=4096, pout=g_xgp
//   fc1:        grid 32  (ntiles=16),  nrows=512,  pout=g_zp
// ============================================================
__global__ __launch_bounds__(128)
void gemmov_k(const float* __restrict__ X, const float* __restrict__ W,
              float* __restrict__ pout_base, int nrows, int ntiles)
{
    extern __shared__ __align__(16) float dsm[];
    float* Wslab = dsm;                                   // 4 * 32*132 = 16896 floats
    float (*Xs)[68] = (float(*)[68])(dsm + 16896);        // 32 x 68
    float (*Ob)[68] = (float(*)[68])(dsm + 16896 + 2176); // 32 x 68

    const int rt = blockIdx.x % ntiles;
    const int cp = blockIdx.x / ntiles;     // 0 or 1 -> chunks cp*4 .. cp*4+3
    const int rb = rt * 32;

    const int t  = threadIdx.x;
    const int tr = t >> 4;
    const int tc = t & 15;

    // prologue: cp.async ALL FOUR chunks' W (4 groups; streams during rec)
#pragma unroll
    for (int u = 0; u < 4; u++) {
        const int chunk = cp * 4 + u;
#pragma unroll
        for (int j = 0; j < 8; j++) {
            int f = t + j * 128;                 // 1024 16B-chunks per W unit
            int row = f >> 5, k16 = f & 31;
            cp_async16(&Wslab[u * 4224 + row * 132 + k16 * 4],
                       &W[(long)(rb + row) * 1024 + chunk * 128 + k16 * 4]);
        }
        CP_COMMIT();
    }

#pragma unroll 1
    for (int u = 0; u < 4; u++) {
        const int chunk = cp * 4 + u;
        float* pout = pout_base + (long)chunk * STEPS * nrows;
        if (u == 0)      CP_WAIT(3);
        else if (u == 1) CP_WAIT(2);
        else if (u == 2) CP_WAIT(1);
        else             CP_WAIT(0);

        float acc[4][4];
#pragma unroll
        for (int i = 0; i < 4; i++)
#pragma unroll
            for (int j = 0; j < 4; j++) acc[i][j] = 0.0f;

#pragma unroll 1
        for (int kt = 0; kt < 4; kt++) {
            const int kglob = chunk * 128 + kt * 32;
            // stage X tile with sentinel poll (h may still be in flight)
#pragma unroll
            for (int i = 0; i < 4; i++) {
                int e = t + i * 128;
                int s = e >> 3, kq = (e & 7) * 4;
                const ull* p = (const ull*)&X[(long)s * HID + kglob + kq];
                ull v0, v1; uint2 q0, q1;
                for (;;) {
                    v0 = ld_relaxed_b64(p); q0 = *(uint2*)&v0;
                    if (q0.x != SENT && q0.y != SENT) break;
                    __nanosleep(200);
                }
                for (;;) {
                    v1 = ld_relaxed_b64(p + 1); q1 = *(uint2*)&v1;
                    if (q1.x != SENT && q1.y != SENT) break;
                    __nanosleep(200);
                }
                float2 f0 = *(float2*)&v0, f1 = *(float2*)&v1;
                Xs[kq + 0][s] = f0.x; Xs[kq + 1][s] = f0.y;
                Xs[kq + 2][s] = f1.x; Xs[kq + 3][s] = f1.y;
            }
            __syncthreads();   // X tile (and, for kt==0, W slab) visible

#pragma unroll
            for (int kq = 0; kq < 8; kq++) {
                float xf[4][4];
#pragma unroll
                for (int q = 0; q < 4; q++) {
                    float4 v = *(const float4*)&Xs[kq * 4 + q][tc * 4];
                    xf[q][0] = v.x; xf[q][1] = v.y; xf[q][2] = v.z; xf[q][3] = v.w;
                }
                float wf[4][4];
#pragma unroll
                for (int i = 0; i < 4; i++) {
                    float4 v = *(const float4*)&Wslab[u * 4224 + (tr * 4 + i) * 132 + kt * 32 + kq * 4];
                    wf[i][0] = v.x; wf[i][1] = v.y; wf[i][2] = v.z; wf[i][3] = v.w;
                }
#pragma unroll
                for (int i = 0; i < 4; i++)
#pragma unroll
                    for (int j = 0; j < 4; j++) {
                        acc[i][j] = fmaf(wf[i][0], xf[0][j], acc[i][j]);
                        acc[i][j] = fmaf(wf[i][1], xf[1][j], acc[i][j]);
                        acc[i][j] = fmaf(wf[i][2], xf[2][j], acc[i][j]);
                        acc[i][j] = fmaf(wf[i][3], xf[3][j], acc[i][j]);
                    }
            }
            __syncthreads();   // Xs reuse guard
        }

        // coalesced output for this chunk
#pragma unroll
        for (int i = 0; i < 4; i++)
            *(float4*)&Ob[tr * 4 + i][tc * 4] =
                make_float4(acc[i][0], acc[i][1], acc[i][2], acc[i][3]);
        __syncthreads();
        const int s_i = t >> 1, half = t & 1;
#pragma unroll
        for (int q = 0; q < 4; q++) {
            const int row = half * 16 + q * 4;
            float4 o = make_float4(Ob[row + 0][s_i], Ob[row + 1][s_i],
                                   Ob[row + 2][s_i], Ob[row + 3][s_i]);
            *(float4*)&pout[(long)s_i * nrows + rb + row] = o;
        }
        __syncthreads();   // Ob reuse guard
    }
}

// ============================================================
// Persistent LSTM recurrence (VERBATIM R16 + PDL trigger line).
// ============================================================
__global__ __launch_bounds__(512, 1)
void lstm_rec(const float* __restrict__ Whh,
              const float* __restrict__ ba, const float* __restrict__ bb,
              int layer)
{
    __shared__ __align__(16) float hsh[HID];
    __shared__ float graw[32];
    __shared__ float gact[32];

    cudaTriggerProgrammaticLaunchCompletion();   // let PDL secondary co-schedule

    float* hseq = layer ? g_h2 : g_h1;
    const int r    = blockIdx.x;
    const int t    = threadIdx.x;
    const int lane = t & 31;
    const int w    = t >> 5;
    const int g    = w & 3;
    const int jh   = w >> 2;
    const int rowbase = (g << 10) + (r << 3) + (jh << 1);

    ull w0[16], w1[16];
#pragma unroll
    for (int p = 0; p < 16; p++) {
        long o = (long)rowbase * 1024 + p * 64 + lane * 2;
        w0[p] = *(const ull*)(Whh + o);
        w1[p] = *(const ull*)(Whh + o + 1024);
    }
    float2 bias = make_float2(0.f, 0.f);
    if (lane == 16) {
        bias.x = ba[rowbase]     + bb[rowbase];
        bias.y = ba[rowbase + 1] + bb[rowbase + 1];
    }
    float creg = 0.0f;
    __syncthreads();

    for (int s = 0; s < STEPS; s++) {
        float2 part = make_float2(0.f, 0.f);
        if (lane < NCH)
            part = *(const float2*)&g_xgp[(long)lane * STEPS * G4 + (long)s * G4 + rowbase];
        else if (lane == 16)
            part = bias;

        float a0 = part.x, a1 = part.y;
        if (s > 0) {
            const ull* src = (const ull*)(hseq + (s - 1) * HID) + t;
            ull hv;
            uint2 u;
            do {
                hv = ld_relaxed_b64(src);
                u  = *(uint2*)&hv;
            } while (u.x == SENT || u.y == SENT);
            ((ull*)hsh)[t] = hv;
            __syncthreads();

            ull acc0 = 0ull, acc1 = 0ull;
#pragma unroll
            for (int p = 0; p < 16; p++) {
                ull h2 = *(const ull*)&hsh[p * 64 + lane * 2];
                acc0 = fma2(w0[p], h2, acc0);
                acc1 = fma2(w1[p], h2, acc1);
            }
            float2 f0 = unpack2(acc0), f1 = unpack2(acc1);
            a0 += f0.x + f0.y;
            a1 += f1.x + f1.y;
        }
#pragma unroll
        for (int o = 16; o > 0; o >>= 1) {
            a0 += __shfl_down_sync(0xffffffffu, a0, o);
            a1 += __shfl_down_sync(0xffffffffu, a1, o);
        }
        if (lane == 0) {
            graw[(jh * 2 + 0) * 4 + g] = a0;
            graw[(jh * 2 + 1) * 4 + g] = a1;
        }
        __syncthreads();

        if (w == 0) {
            float v = graw[lane];
            gact[lane] = ((lane & 3) == 2) ? tanhfast(v) : sigf(v);
            __syncwarp();
            if (lane < 8) {
                float iv = gact[lane * 4 + 0];
                float fv = gact[lane * 4 + 1];
                float gv = gact[lane * 4 + 2];
                float ov = gact[lane * 4 + 3];
                creg = fmaf(fv, creg, iv * gv);
                st_relaxed_f32(&hseq[s * HID + r * 8 + lane], ov * tanhfast(creg));
            }
        }
    }
}

// ============================================================
// FC2 fused with fc1 partial-reduce + bias + ReLU. One CTA per s.
// ============================================================
__global__ __launch_bounds__(128)
void fc2_k(const float* __restrict__ W2, const float* __restrict__ b2,
           const float* __restrict__ b1, float* __restrict__ out)
{
    __shared__ __align__(16) float zsh[512];
    const int s = blockIdx.x;
    const int t = threadIdx.x, lane = t & 31, w = t >> 5;

    {
        const long base = (long)s * 512 + t * 4;
        float4 z = *(const float4*)&b1[t * 4];
#pragma unroll
        for (int c = 0; c < NCH; c++) {
            float4 p = *(const float4*)&g_zp[base + (long)c * STEPS * 512];
            z.x += p.x; z.y += p.y; z.z += p.z; z.w += p.w;
        }
        z.x = fmaxf(z.x, 0.f); z.y = fmaxf(z.y, 0.f);
        z.z = fmaxf(z.z, 0.f); z.w = fmaxf(z.w, 0.f);
        *(float4*)&zsh[t * 4] = z;
    }
    __syncthreads();

    for (int c = w; c < CC; c += 4) {
        float acc = 0.f;
#pragma unroll
        for (int k = 0; k < 16; k++)
            acc = fmaf(zsh[k * 32 + lane], W2[c * 512 + k * 32 + lane], acc);
#pragma unroll
        for (int o = 16; o > 0; o >>= 1)
            acc += __shfl_down_sync(0xffffffffu, acc, o);
        if (lane == 0) out[s * CC + c] = acc + b2[c];
    }
}

// ============================================================
static void launch_gemmov_pdl(const float* X, const float* W, float* pout,
                              int nrows, int ntiles, int grid)
{
    static_assert(sizeof(float) == 4, "");
    const size_t dsm = (16896 + 2176 + 2176) * sizeof(float);   // 84992 B
    cudaFuncSetAttribute(gemmov_k, cudaFuncAttributeMaxDynamicSharedMemorySize, (int)dsm);

    cudaLaunchConfig_t cfg = {};
    cfg.gridDim  = dim3(grid, 1, 1);
    cfg.blockDim = dim3(128, 1, 1);
    cfg.dynamicSmemBytes = dsm;
    cfg.stream = 0;
    cudaLaunchAttribute at[1];
    at[0].id = cudaLaunchAttributeProgrammaticStreamSerialization;
    at[0].val.programmaticStreamSerializationAllowed = 1;
    cfg.attrs = at;
    cfg.numAttrs = 1;
    cudaLaunchKernelEx(&cfg, gemmov_k, X, W, pout, nrows, ntiles);
}

extern "C" void kernel_launch(void* const* d_in, const int* in_sizes, int n_in,
                              void* d_out, int out_size)
{
    const float* x    = (const float*)d_in[0];
    const float* Wih0 = (const float*)d_in[1];
    const float* Whh0 = (const float*)d_in[2];
    const float* bih0 = (const float*)d_in[3];
    const float* bhh0 = (const float*)d_in[4];
    const float* Wih1 = (const float*)d_in[5];
    const float* Whh1 = (const float*)d_in[6];
    const float* bih1 = (const float*)d_in[7];
    const float* bhh1 = (const float*)d_in[8];
    const float* W1   = (const float*)d_in[9];
    const float* b1   = (const float*)d_in[10];
    const float* W2   = (const float*)d_in[11];
    const float* b2   = (const float*)d_in[12];
    float* out = (float*)d_out;

    float* h1p = nullptr; float* h2p = nullptr; float* xgp = nullptr; float* zpp = nullptr;
    cudaGetSymbolAddress((void**)&h1p, g_h1);
    cudaGetSymbolAddress((void**)&h2p, g_h2);
    cudaGetSymbolAddress((void**)&xgp, g_xgp);
    cudaGetSymbolAddress((void**)&zpp, g_zp);

    gemm0_k<<<1024, 128>>>(x, Wih0);                 // sentinel fill + xg0 partials
    lstm_rec<<<NB, 512>>>(Whh0, bih0, bhh0, 0);      // layer-1 rec (PDL trigger)
    launch_gemmov_pdl(h1p, Wih1, xgp, G4, 128, 256); // xg1 partials, overlapped w/ rec0
    lstm_rec<<<NB, 512>>>(Whh1, bih1, bhh1, 1);      // layer-2 rec (PDL trigger)
    launch_gemmov_pdl(h2p, W1, zpp, 512, 16, 32);    // fc1 partials, overlapped w/ rec1
    fc2_k<<<64, 128>>>(W2, b2, b1, out);             // reduce+relu+fc2
}